// round 7
// baseline (speedup 1.0000x reference)
#include <cuda_runtime.h>
#include <cstdint>

#define B_DIM 64
#define N_DIM 1024
#define C_DIM 256
#define NTOK (B_DIM * N_DIM)
#define OUT_IDX  ((size_t)B_DIM * N_DIM * C_DIM)
#define OUT_LOSS (OUT_IDX + (size_t)B_DIM * N_DIM)
#define EPS_AMB 3e-4f
#define TOK 64
#define KTOT 3840          // total codebook rows (256+512+1024+2048)

// dynamic smem: zd dup tile [256 c][64 tok dup pairs] = 128KB, cb 2x32KB
#define SM_CB   131072
#define SM_DYN  196608

// ---- device scratch (no cudaMalloc allowed) ----
__device__ float g_cnorm[KTOT];
__device__ float g_partial[1024];
__device__ int   g_idx[NTOK];
__device__ int   g_amb[NTOK];
__device__ int   g_cnt;
__device__ float g_cbT[256 * KTOT];   // transposed codebooks: [c][global k]

// ---- helpers ----
__device__ __forceinline__ uint32_t smem_u32(const void* p) {
    uint32_t a;
    asm("{ .reg .u64 t; cvta.to.shared.u64 t, %1; cvt.u32.u64 %0, t; }" : "=r"(a) : "l"(p));
    return a;
}
#define CP16(dst, src)  asm volatile("cp.async.cg.shared.global [%0], [%1], 16;" :: "r"(dst), "l"(src) : "memory")
#define CP_COMMIT()     asm volatile("cp.async.commit_group;" ::: "memory")
#define CP_WAIT1()      asm volatile("cp.async.wait_group 1;" ::: "memory")
#define CP_WAIT0()      asm volatile("cp.async.wait_group 0;" ::: "memory")
#define FFMA2(acc, a, b) asm("fma.rn.f32x2 %0, %1, %2, %0;" : "+l"(acc) : "l"(a), "l"(b))

__device__ __forceinline__ void pick_cb(int e, const float* cb0, const float* cb1,
                                        const float* cb2, const float* cb3,
                                        const float*& cb, int& K, int& coff) {
    if (e == 0)      { cb = cb0; K = 256;  coff = 0;    }
    else if (e == 1) { cb = cb1; K = 512;  coff = 256;  }
    else if (e == 2) { cb = cb2; K = 1024; coff = 768;  }
    else             { cb = cb3; K = 2048; coff = 1792; }
}

// ---------------------------------------------------------------------------
// K0a: transpose codebooks into g_cbT[c][global_k]
// ---------------------------------------------------------------------------
__global__ void transpose_kernel(const float* __restrict__ cb0, const float* __restrict__ cb1,
                                 const float* __restrict__ cb2, const float* __restrict__ cb3)
{
    int idx = blockIdx.x * 256 + threadIdx.x;   // 3840*64 total
    int row = idx >> 6, c4 = idx & 63;
    const float* base; int local;
    if (row < 256)       { base = cb0; local = row;        }
    else if (row < 768)  { base = cb1; local = row - 256;  }
    else if (row < 1792) { base = cb2; local = row - 768;  }
    else                 { base = cb3; local = row - 1792; }
    float4 v = ((const float4*)(base + (size_t)local * C_DIM))[c4];
    float x[4] = {v.x, v.y, v.z, v.w};
    #pragma unroll
    for (int i = 0; i < 4; i++)
        g_cbT[(size_t)(c4 * 4 + i) * KTOT + row] = x[i];
}

// ---------------------------------------------------------------------------
// K0b: codebook row norms (fp64 -> fp32) + reset ambiguous counter
// ---------------------------------------------------------------------------
__global__ void cnorm_kernel(const float* __restrict__ cb0, const float* __restrict__ cb1,
                             const float* __restrict__ cb2, const float* __restrict__ cb3)
{
    if (blockIdx.x == 0 && threadIdx.x == 0) g_cnt = 0;
    int row  = blockIdx.x * 8 + (threadIdx.x >> 5);
    int lane = threadIdx.x & 31;
    const float* base; int local;
    if (row < 256)       { base = cb0; local = row;        }
    else if (row < 768)  { base = cb1; local = row - 256;  }
    else if (row < 1792) { base = cb2; local = row - 768;  }
    else                 { base = cb3; local = row - 1792; }
    const float4* p = (const float4*)(base + (size_t)local * C_DIM);
    double s = 0.0;
    #pragma unroll
    for (int i = 0; i < 2; i++) {
        float4 v = p[lane + i * 32];
        s += (double)v.x * v.x + (double)v.y * v.y + (double)v.z * v.z + (double)v.w * v.w;
    }
    #pragma unroll
    for (int o = 16; o; o >>= 1) s += __shfl_xor_sync(0xffffffffu, s, o);
    if (lane == 0) g_cnorm[row] = (float)s;
}

// ---------------------------------------------------------------------------
// K1: f32x2 SIMT distance GEMM + per-token top-2 + ambiguity flags.
// CTA: 64 tokens x full K, 256 threads. warp w: tokens 8w..8w+7;
// lane: codes {2*lane+64j, +1}. score(k) = ||c_k||^2 - 2 z.c_k
// ---------------------------------------------------------------------------
__global__ __launch_bounds__(256, 1) void vq_f32x2(
    const float* __restrict__ z_e, const int* __restrict__ expert_idx)
{
    extern __shared__ __align__(16) char dsm[];
    const uint32_t sa = smem_u32(dsm);

    const int tid = threadIdx.x, w = tid >> 5, lane = tid & 31;
    const int b = blockIdx.y, t0 = blockIdx.x * TOK;

    int e = expert_idx[b];
    int K, coff;
    if (e == 0)      { K = 256;  coff = 0;    }
    else if (e == 1) { K = 512;  coff = 256;  }
    else if (e == 2) { K = 1024; coff = 768;  }
    else             { K = 2048; coff = 1792; }

    // ---- stage z tile duplicated: zd[c][tok dup pairs], quad XOR swizzle ----
    const float4* zin = (const float4*)(z_e + ((size_t)b * N_DIM + t0) * C_DIM);
    #pragma unroll
    for (int it = 0; it < 16; it++) {
        int idx = it * 256 + tid;
        int c4 = idx & 63, t = idx >> 6;
        float4 v = zin[t * 64 + c4];
        float x[4] = {v.x, v.y, v.z, v.w};
        uint32_t qsw = ((uint32_t)(t >> 1)) ^ ((uint32_t)c4 & 7u);
        uint32_t off0 = (qsw << 4) + (uint32_t)((t & 1) << 3);
        #pragma unroll
        for (int i = 0; i < 4; i++) {
            uint32_t c = (uint32_t)(c4 * 4 + i);
            *(float2*)(dsm + (c << 9) + off0) = make_float2(x[i], x[i]);
        }
    }

    // ---- cb chunk staging: 32 c-rows x 1KB via cp.async from g_cbT ----
    auto stage_cb = [&](int s2) {
        int kc = (s2 >> 3) << 8;
        int cg = (s2 & 7) * 32;
        uint32_t dbuf = sa + SM_CB + (uint32_t)((s2 & 1) ? 32768 : 0);
        const float* srcb = g_cbT + (size_t)cg * KTOT + coff + kc;
        #pragma unroll
        for (int it = 0; it < 8; it++) {
            int idx = it * 256 + tid;          // 0..2047
            int row = idx >> 6;                // c within stage
            int seg = idx & 63;                // 16B seg
            CP16(dbuf + (uint32_t)(row * 1024 + seg * 16),
                 srcb + (size_t)row * KTOT + seg * 4);
        }
    };

    stage_cb(0);
    CP_COMMIT();

    unsigned long long acc[8][4];
    float v1[8], v2[8]; int i1[8];
    #pragma unroll
    for (int r = 0; r < 8; r++) { v1[r] = 3.4e38f; v2[r] = 3.4e38f; i1[r] = 0; }

    const int S = (K >> 8) * 8;
    for (int s = 0; s < S; s++) {
        if (s + 1 < S) { stage_cb(s + 1); CP_COMMIT(); CP_WAIT1(); }
        else           { CP_WAIT0(); }
        __syncthreads();                       // buffer (s&1) ready; z staged

        if ((s & 7) == 0) {
            #pragma unroll
            for (int r = 0; r < 8; r++)
                #pragma unroll
                for (int j = 0; j < 4; j++) acc[r][j] = 0ull;
        }

        const uint32_t cbufo = (uint32_t)SM_CB + (uint32_t)((s & 1) ? 32768 : 0);
        const int cg0 = (s & 7) * 32;
        #pragma unroll 4
        for (int cc = 0; cc < 32; cc++) {
            uint32_t c = (uint32_t)(cg0 + cc);
            uint32_t kappa = (c >> 2) & 7u;
            uint32_t zo = c << 9;
            ulonglong2 za = *(const ulonglong2*)(dsm + zo + ((((uint32_t)(4*w+0) ^ kappa) << 4)));
            ulonglong2 zb = *(const ulonglong2*)(dsm + zo + ((((uint32_t)(4*w+1) ^ kappa) << 4)));
            ulonglong2 zc = *(const ulonglong2*)(dsm + zo + ((((uint32_t)(4*w+2) ^ kappa) << 4)));
            ulonglong2 zd = *(const ulonglong2*)(dsm + zo + ((((uint32_t)(4*w+3) ^ kappa) << 4)));
            unsigned long long zt[8] = {za.x, za.y, zb.x, zb.y, zc.x, zc.y, zd.x, zd.y};
            uint32_t co = cbufo + ((uint32_t)cc << 10);
            unsigned long long cp[4];
            #pragma unroll
            for (int j = 0; j < 4; j++)
                cp[j] = *(const unsigned long long*)(dsm + co + (uint32_t)((2*lane + 64*j) << 2));
            #pragma unroll
            for (int r = 0; r < 8; r++)
                #pragma unroll
                for (int j = 0; j < 4; j++)
                    FFMA2(acc[r][j], zt[r], cp[j]);
        }

        if ((s & 7) == 7) {                    // chunk epilogue (regs only)
            int kc = (s >> 3) << 8;
            #pragma unroll
            for (int j = 0; j < 4; j++) {
                int kk = kc + 2 * lane + 64 * j;
                float2 cn = __ldg((const float2*)(g_cnorm + coff + kk));
                #pragma unroll
                for (int r = 0; r < 8; r++) {
                    float lo = __uint_as_float((uint32_t)acc[r][j]);
                    float hi = __uint_as_float((uint32_t)(acc[r][j] >> 32));
                    float s0 = fmaf(-2.f, lo, cn.x);
                    float s1 = fmaf(-2.f, hi, cn.y);
                    if (s0 < v1[r]) { v2[r] = v1[r]; v1[r] = s0; i1[r] = kk; }
                    else            { v2[r] = fminf(v2[r], s0); }
                    if (s1 < v1[r]) { v2[r] = v1[r]; v1[r] = s1; i1[r] = kk + 1; }
                    else            { v2[r] = fminf(v2[r], s1); }
                }
            }
        }
        __syncthreads();                       // all done with buffer before overwrite
    }

    // merge top-2 across 32 lanes (lanes hold disjoint code groups, same tokens)
    #pragma unroll
    for (int o = 16; o; o >>= 1) {
        #pragma unroll
        for (int r = 0; r < 8; r++) {
            float ov1 = __shfl_xor_sync(0xffffffffu, v1[r], o);
            int   oi1 = __shfl_xor_sync(0xffffffffu, i1[r], o);
            float ov2 = __shfl_xor_sync(0xffffffffu, v2[r], o);
            float hi = fmaxf(v1[r], ov1);
            float nv2 = fminf(fminf(v2[r], ov2), hi);
            if (ov1 < v1[r] || (ov1 == v1[r] && oi1 < i1[r])) { v1[r] = ov1; i1[r] = oi1; }
            v2[r] = nv2;
        }
    }
    if (lane == 0) {
        #pragma unroll
        for (int r = 0; r < 8; r++) {
            int tok = b * N_DIM + t0 + w * 8 + r;
            g_idx[tok] = i1[r];
            if (v2[r] - v1[r] <= EPS_AMB) {
                int pos = atomicAdd(&g_cnt, 1);
                g_amb[pos] = tok;
            }
        }
    }
}

// ---------------------------------------------------------------------------
// K2: exact resolver (validated round 2): emulate reference fp32 rounding
// ---------------------------------------------------------------------------
__global__ __launch_bounds__(256) void resolve_kernel(
    const float* __restrict__ z_e, const int* __restrict__ expert_idx,
    const float* __restrict__ cb0, const float* __restrict__ cb1,
    const float* __restrict__ cb2, const float* __restrict__ cb3)
{
    __shared__ float zrow[8][C_DIM];
    const int wid = threadIdx.x >> 5, lane = threadIdx.x & 31;
    const int gw = blockIdx.x * 8 + wid;
    const int nw = gridDim.x * 8;
    const int cnt = g_cnt;

    for (int it = gw; it < cnt; it += nw) {
        int tok = g_amb[it];
        int b = tok >> 10;
        const float* cb; int K, coff;
        pick_cb(expert_idx[b], cb0, cb1, cb2, cb3, cb, K, coff);

        const float4* zr = (const float4*)(z_e + (size_t)tok * C_DIM);
        #pragma unroll
        for (int r = 0; r < 2; r++) {
            float4 v = zr[lane + r * 32];
            int c = (lane + r * 32) * 4;
            zrow[wid][c + 0] = v.x; zrow[wid][c + 1] = v.y;
            zrow[wid][c + 2] = v.z; zrow[wid][c + 3] = v.w;
        }
        __syncwarp();

        double zn = 0.0;
        #pragma unroll
        for (int c = 0; c < 8; c++) {
            double z = (double)zrow[wid][lane * 8 + c];
            zn += z * z;
        }
        #pragma unroll
        for (int o = 16; o; o >>= 1) zn += __shfl_xor_sync(0xffffffffu, zn, o);

        const double invGs = (zn >= 256.0) ? 32768.0 : 65536.0;
        const double Gs = 1.0 / invGs;

        double bestm = 1e300; int besti = 0x7fffffff;
        for (int k0 = 0; k0 < K; k0 += 32) {
            int k = k0 + lane;
            const float* cr = cb + (size_t)k * C_DIM;
            float acc = 0.f;
            #pragma unroll 8
            for (int c = 0; c < C_DIM; c++)
                acc = fmaf(zrow[wid][c], __ldg(&cr[c]), acc);
            float cn32 = __ldg(&g_cnorm[coff + k]);
            double dot2 = 2.0 * (double)acc;
            double d = zn + (double)cn32 - dot2;
            double invGd = (d >= 256.0) ? 32768.0 : 65536.0;
            double Gd = 1.0 / invGd;
            double m = rint((double)cn32 * invGs) * Gs - rint(dot2 * invGd) * Gd;
            if (m < bestm || (m == bestm && k < besti)) { bestm = m; besti = k; }
        }
        #pragma unroll
        for (int o = 16; o; o >>= 1) {
            double om = __shfl_xor_sync(0xffffffffu, bestm, o);
            int    oi = __shfl_xor_sync(0xffffffffu, besti, o);
            if (om < bestm || (om == bestm && oi < besti)) { bestm = om; besti = oi; }
        }
        if (lane == 0) g_idx[tok] = besti;
    }
}

// ---------------------------------------------------------------------------
// K3: gather z_q, straight-through, indices output, SSE partials
// ---------------------------------------------------------------------------
__global__ __launch_bounds__(256) void output_kernel(
    const float* __restrict__ z_e, const int* __restrict__ expert_idx,
    const float* __restrict__ cb0, const float* __restrict__ cb1,
    const float* __restrict__ cb2, const float* __restrict__ cb3,
    float* __restrict__ out)
{
    __shared__ float wsum[8];
    const int tid = threadIdx.x;
    const int b   = blockIdx.y;
    const int t0  = blockIdx.x * TOK;

    const float* cb; int K, coff;
    pick_cb(expert_idx[b], cb0, cb1, cb2, cb3, cb, K, coff);

    const float4* zin = (const float4*)(z_e + ((size_t)b * N_DIM + t0) * C_DIM);

    if (tid < TOK) {
        int idx = g_idx[b * N_DIM + t0 + tid];
        out[OUT_IDX + (size_t)b * N_DIM + t0 + tid] = (float)idx;
    }

    const int warp = tid >> 5, lane = tid & 31;
    float sq = 0.f;
    for (int s8 = 0; s8 < 8; s8++) {
        int t = warp * 8 + s8;
        int idx = g_idx[b * N_DIM + t0 + t];
        const float4* crow = (const float4*)(cb + (size_t)idx * C_DIM);
        const float4* zrow = zin + (size_t)t * 64;
        float4* orow = (float4*)(out + ((size_t)b * N_DIM + t0 + t) * C_DIM);
        #pragma unroll
        for (int r = 0; r < 2; r++) {
            int c4 = lane + r * 32;
            float4 q = crow[c4], z = zrow[c4];
            float dx = q.x - z.x, dy = q.y - z.y, dz = q.z - z.z, dw = q.w - z.w;
            sq += dx * dx + dy * dy + dz * dz + dw * dw;
            float4 o; o.x = z.x + dx; o.y = z.y + dy; o.z = z.z + dz; o.w = z.w + dw;
            orow[c4] = o;
        }
    }
    #pragma unroll
    for (int o = 16; o; o >>= 1) sq += __shfl_xor_sync(0xffffffffu, sq, o);
    if (lane == 0) wsum[warp] = sq;
    __syncthreads();
    if (tid == 0) {
        float tot = 0.f;
        #pragma unroll
        for (int w = 0; w < 8; w++) tot += wsum[w];
        g_partial[blockIdx.y * 16 + blockIdx.x] = tot;
    }
}

// ---------------------------------------------------------------------------
// K4: vq_loss = 1.25 * SSE / 2^32
// ---------------------------------------------------------------------------
__global__ void finalize_kernel(float* __restrict__ out)
{
    __shared__ float s[256];
    float a = 0.f;
    for (int i = threadIdx.x; i < 1024; i += 256) a += g_partial[i];
    s[threadIdx.x] = a;
    __syncthreads();
    for (int o = 128; o; o >>= 1) {
        if (threadIdx.x < o) s[threadIdx.x] += s[threadIdx.x + o];
        __syncthreads();
    }
    if (threadIdx.x == 0)
        out[OUT_LOSS] = s[0] * (float)(1.25 / 4294967296.0);
}

// ---------------------------------------------------------------------------
extern "C" void kernel_launch(void* const* d_in, const int* in_sizes, int n_in,
                              void* d_out, int out_size)
{
    const float* z_e        = (const float*)d_in[0];
    const int*   expert_idx = (const int*)  d_in[1];
    const float* cb0        = (const float*)d_in[2];
    const float* cb1        = (const float*)d_in[3];
    const float* cb2        = (const float*)d_in[4];
    const float* cb3        = (const float*)d_in[5];
    float* out = (float*)d_out;

    cudaFuncSetAttribute(vq_f32x2, cudaFuncAttributeMaxDynamicSharedMemorySize, SM_DYN);

    transpose_kernel<<<960, 256>>>(cb0, cb1, cb2, cb3);
    cnorm_kernel<<<480, 256>>>(cb0, cb1, cb2, cb3);

    dim3 gmain(N_DIM / TOK, B_DIM);
    vq_f32x2<<<gmain, 256, SM_DYN>>>(z_e, expert_idx);

    resolve_kernel<<<128, 256>>>(z_e, expert_idx, cb0, cb1, cb2, cb3);

    output_kernel<<<gmain, 256>>>(z_e, expert_idx, cb0, cb1, cb2, cb3, out);

    finalize_kernel<<<1, 256>>>(out);
}